// round 8
// baseline (speedup 1.0000x reference)
#include <cuda_runtime.h>
#include <cstddef>

#define HW   4096
#define CIN  256
#define CHD  128
#define BB   4
#define MT   128   // query tile per CTA
#define NT   64    // key tile per iteration

// Scratch (allocation-free device globals)
__device__ float g_Q[BB * HW * CHD];   // [b][m][c]  (transposed, tf32)
__device__ float g_K[BB * HW * CHD];   // [b][n][c]  (transposed, tf32)
__device__ float g_V[BB * CIN * HW];   // [b][cv][n] (tf32)

__device__ __forceinline__ float to_tf32(float x) {
    unsigned u;
    asm("cvt.rna.tf32.f32 %0, %1;" : "=r"(u) : "f"(x));
    return __uint_as_float(u);
}

__device__ __forceinline__ void mma_tf32(float c[4],
                                         unsigned a0, unsigned a1, unsigned a2, unsigned a3,
                                         unsigned b0, unsigned b1) {
    asm volatile(
        "mma.sync.aligned.m16n8k8.row.col.f32.tf32.tf32.f32 "
        "{%0,%1,%2,%3}, {%4,%5,%6,%7}, {%8,%9}, {%0,%1,%2,%3};\n"
        : "+f"(c[0]), "+f"(c[1]), "+f"(c[2]), "+f"(c[3])
        : "r"(a0), "r"(a1), "r"(a2), "r"(a3), "r"(b0), "r"(b1));
}

__device__ __forceinline__ void cp_async16(unsigned dst_smem, const void* src) {
    asm volatile("cp.async.cg.shared.global [%0], [%1], 16;\n"
                 :: "r"(dst_smem), "l"(src));
}
__device__ __forceinline__ void cp_async_commit_wait() {
    asm volatile("cp.async.commit_group;\n");
    asm volatile("cp.async.wait_group 0;\n");
}

// ---------------------------------------------------------------------------
// V projection: Out[b, o, n] = sum_c W[o,c] X[b,c,n] + bias[o]   (tf32-rounded)
// ---------------------------------------------------------------------------
__global__ __launch_bounds__(256)
void proj_kernel(const float* __restrict__ W, const float* __restrict__ bias,
                 const float* __restrict__ X, float* __restrict__ Out, int O) {
    __shared__ float Ws[32][65];   // [k][o]
    __shared__ float Xs[32][64];   // [k][n]

    const int tid = threadIdx.x;
    const int n0  = blockIdx.x * 64;
    const int o0  = blockIdx.y * 64;
    const int b   = blockIdx.z;
    const float* Xb = X + (size_t)b * CIN * HW;

    const int tx = tid & 15;       // n quad
    const int ty = tid >> 4;       // o quad
    float acc[4][4] = {};

    for (int k0 = 0; k0 < CIN; k0 += 32) {
        {
            int r = tid >> 2;
            int q = (tid & 3) * 8;
            float4 wa = *(const float4*)&W[(size_t)(o0 + r) * CIN + k0 + q];
            float4 wb = *(const float4*)&W[(size_t)(o0 + r) * CIN + k0 + q + 4];
            Ws[q + 0][r] = wa.x; Ws[q + 1][r] = wa.y;
            Ws[q + 2][r] = wa.z; Ws[q + 3][r] = wa.w;
            Ws[q + 4][r] = wb.x; Ws[q + 5][r] = wb.y;
            Ws[q + 6][r] = wb.z; Ws[q + 7][r] = wb.w;
        }
        {
            int c  = tid >> 3;
            int nq = (tid & 7) * 8;
            const float* src = &Xb[(size_t)(k0 + c) * HW + n0 + nq];
            *(float4*)&Xs[c][nq]     = *(const float4*)&src[0];
            *(float4*)&Xs[c][nq + 4] = *(const float4*)&src[4];
        }
        __syncthreads();

        #pragma unroll
        for (int kk = 0; kk < 32; kk++) {
            float4 xv = *(float4*)&Xs[kk][tx * 4];
            float w0 = Ws[kk][ty * 4 + 0];
            float w1 = Ws[kk][ty * 4 + 1];
            float w2 = Ws[kk][ty * 4 + 2];
            float w3 = Ws[kk][ty * 4 + 3];
            acc[0][0] += w0 * xv.x; acc[0][1] += w0 * xv.y; acc[0][2] += w0 * xv.z; acc[0][3] += w0 * xv.w;
            acc[1][0] += w1 * xv.x; acc[1][1] += w1 * xv.y; acc[1][2] += w1 * xv.z; acc[1][3] += w1 * xv.w;
            acc[2][0] += w2 * xv.x; acc[2][1] += w2 * xv.y; acc[2][2] += w2 * xv.z; acc[2][3] += w2 * xv.w;
            acc[3][0] += w3 * xv.x; acc[3][1] += w3 * xv.y; acc[3][2] += w3 * xv.z; acc[3][3] += w3 * xv.w;
        }
        __syncthreads();
    }

    #pragma unroll
    for (int i = 0; i < 4; i++) {
        int o = o0 + ty * 4 + i;
        float bi = bias[o];
        float4 r;
        r.x = to_tf32(acc[i][0] + bi); r.y = to_tf32(acc[i][1] + bi);
        r.z = to_tf32(acc[i][2] + bi); r.w = to_tf32(acc[i][3] + bi);
        *(float4*)&Out[((size_t)b * O + o) * HW + n0 + tx * 4] = r;
    }
}

// ---------------------------------------------------------------------------
// Q/K projection, transposed output: Out[b, n, o] = sum_c W[o,c] X[b,c,n] + b[o]
// ---------------------------------------------------------------------------
__global__ __launch_bounds__(256)
void proj_t_kernel(const float* __restrict__ W, const float* __restrict__ bias,
                   const float* __restrict__ X, float* __restrict__ Out, int O) {
    __shared__ float Ws[32][68];   // [k][o]
    __shared__ float Xs[32][64];   // [k][n]

    const int tid = threadIdx.x;
    const int n0  = blockIdx.x * 64;
    const int o0  = blockIdx.y * 64;
    const int b   = blockIdx.z;
    const float* Xb = X + (size_t)b * CIN * HW;

    const int tx = tid & 15;       // o quad
    const int ty = tid >> 4;       // n quad
    float acc[4][4] = {};          // [n-sub][o-vec]

    for (int k0 = 0; k0 < CIN; k0 += 32) {
        {
            int r = tid >> 2;
            int q = (tid & 3) * 8;
            float4 wa = *(const float4*)&W[(size_t)(o0 + r) * CIN + k0 + q];
            float4 wb = *(const float4*)&W[(size_t)(o0 + r) * CIN + k0 + q + 4];
            Ws[q + 0][r] = wa.x; Ws[q + 1][r] = wa.y;
            Ws[q + 2][r] = wa.z; Ws[q + 3][r] = wa.w;
            Ws[q + 4][r] = wb.x; Ws[q + 5][r] = wb.y;
            Ws[q + 6][r] = wb.z; Ws[q + 7][r] = wb.w;
        }
        {
            int c  = tid >> 3;
            int nq = (tid & 7) * 8;
            const float* src = &Xb[(size_t)(k0 + c) * HW + n0 + nq];
            *(float4*)&Xs[c][nq]     = *(const float4*)&src[0];
            *(float4*)&Xs[c][nq + 4] = *(const float4*)&src[4];
        }
        __syncthreads();

        #pragma unroll
        for (int kk = 0; kk < 32; kk++) {
            float4 wv = *(float4*)&Ws[kk][tx * 4];
            float x0 = Xs[kk][ty * 4 + 0];
            float x1 = Xs[kk][ty * 4 + 1];
            float x2 = Xs[kk][ty * 4 + 2];
            float x3 = Xs[kk][ty * 4 + 3];
            acc[0][0] += x0 * wv.x; acc[0][1] += x0 * wv.y; acc[0][2] += x0 * wv.z; acc[0][3] += x0 * wv.w;
            acc[1][0] += x1 * wv.x; acc[1][1] += x1 * wv.y; acc[1][2] += x1 * wv.z; acc[1][3] += x1 * wv.w;
            acc[2][0] += x2 * wv.x; acc[2][1] += x2 * wv.y; acc[2][2] += x2 * wv.z; acc[2][3] += x2 * wv.w;
            acc[3][0] += x3 * wv.x; acc[3][1] += x3 * wv.y; acc[3][2] += x3 * wv.z; acc[3][3] += x3 * wv.w;
        }
        __syncthreads();
    }

    float4 bb = *(const float4*)&bias[o0 + tx * 4];
    #pragma unroll
    for (int i = 0; i < 4; i++) {
        int n = n0 + ty * 4 + i;
        float4 r;
        r.x = to_tf32(acc[i][0] + bb.x); r.y = to_tf32(acc[i][1] + bb.y);
        r.z = to_tf32(acc[i][2] + bb.z); r.w = to_tf32(acc[i][3] + bb.w);
        *(float4*)&Out[((size_t)b * HW + n) * O + o0 + tx * 4] = r;
    }
}

// ---------------------------------------------------------------------------
// Flash attention with tf32 mma.sync + residual.  512 threads / 16 warps.
// grid (HW/128, B) = 128 CTAs (1 wave), ~205KB smem, 1 CTA/SM.
//
// S-phase : S[128m][64n]  warps 8m x 2n,  warp tile 16x32
// O-phase : O[128m][256c] warps 8m x 2cv, warp tile 16x128
// ---------------------------------------------------------------------------
__global__ __launch_bounds__(512)
void attn_kernel(const float* __restrict__ resid, float* __restrict__ out) {
    extern __shared__ float sm[];
    float* Qs     = sm;                 // [128][132]  16896
    float* Ks     = Qs + 128 * 132;     // [64][132]    8448
    float* Vs     = Ks + 64 * 132;      // [256][68]   17408
    float* Ps     = Vs + 256 * 68;      // [128][68]    8704
    float* rowM   = Ps + 128 * 68;      // 128
    float* rowL   = rowM + 128;         // 128
    float* alphaS = rowL + 128;         // 128
    float* pmax   = alphaS + 128;       // [2][128]
    float* psum   = pmax + 256;         // [2][128]

    const int tid  = threadIdx.x;
    const int b    = blockIdx.y;
    const int m0g  = blockIdx.x * MT;
    const int w    = tid >> 5;
    const int lane = tid & 31;
    const int g    = lane >> 2;
    const int t    = lane & 3;
    const int wm   = w >> 1;       // m-eighth (both phases)
    const int wh   = w & 1;        // n-half (S) / cv-half (O)
    const int m0w  = wm * 16;
    const int r0   = m0w + g;

    const float* Q = g_Q + (size_t)b * HW * CHD;
    const float* K = g_K + (size_t)b * HW * CHD;
    const float* V = g_V + (size_t)b * CIN * HW;

    // Load Q tile [128][128] -> Qs (rows padded to 132) via cp.async
    for (int idx = tid; idx < 128 * 32; idx += 512) {
        int r = idx >> 5, c4 = (idx & 31) << 2;
        cp_async16((unsigned)__cvta_generic_to_shared(&Qs[r * 132 + c4]),
                   &Q[(size_t)(m0g + r) * CHD + c4]);
    }
    if (tid < 128) { rowM[tid] = -1e30f; rowL[tid] = 0.0f; }
    cp_async_commit_wait();

    float oacc[16][4];
    #pragma unroll
    for (int cf = 0; cf < 16; cf++)
        #pragma unroll
        for (int e = 0; e < 4; e++) oacc[cf][e] = 0.0f;

    for (int nt = 0; nt < HW; nt += NT) {
        __syncthreads();   // prior O-MMA (reads Ps/Vs/Ks) done; Qs ready on iter 0

        // K tile [64][128] -> Ks
        for (int idx = tid; idx < 64 * 32; idx += 512) {
            int r = idx >> 5, c4 = (idx & 31) << 2;
            cp_async16((unsigned)__cvta_generic_to_shared(&Ks[r * 132 + c4]),
                       &K[(size_t)(nt + r) * CHD + c4]);
        }
        // V tile [256][64] -> Vs (rows padded to 68)
        for (int idx = tid; idx < 256 * 16; idx += 512) {
            int r = idx >> 4, c4 = (idx & 15) << 2;
            cp_async16((unsigned)__cvta_generic_to_shared(&Vs[r * 68 + c4]),
                       &V[(size_t)r * HW + nt + c4]);
        }
        cp_async_commit_wait();
        __syncthreads();

        // ---- S = Q Kt  (warp tile 16x32) ----
        float sacc[4][4] = {};
        const int n0w = wh * 32;
        #pragma unroll
        for (int ks = 0; ks < 16; ks++) {
            int kc = ks * 8;
            unsigned a0 = __float_as_uint(Qs[r0 * 132 + kc + t]);
            unsigned a1 = __float_as_uint(Qs[(r0 + 8) * 132 + kc + t]);
            unsigned a2 = __float_as_uint(Qs[r0 * 132 + kc + t + 4]);
            unsigned a3 = __float_as_uint(Qs[(r0 + 8) * 132 + kc + t + 4]);
            #pragma unroll
            for (int nf = 0; nf < 4; nf++) {
                int n = n0w + nf * 8 + g;
                unsigned b0 = __float_as_uint(Ks[n * 132 + kc + t]);
                unsigned b1 = __float_as_uint(Ks[n * 132 + kc + t + 4]);
                mma_tf32(sacc[nf], a0, a1, a2, a3, b0, b1);
            }
        }

        // ---- softmax: per-warp partial row max ----
        {
            float lm0 = -1e30f, lm1 = -1e30f;
            #pragma unroll
            for (int nf = 0; nf < 4; nf++) {
                lm0 = fmaxf(lm0, fmaxf(sacc[nf][0], sacc[nf][1]));
                lm1 = fmaxf(lm1, fmaxf(sacc[nf][2], sacc[nf][3]));
            }
            lm0 = fmaxf(lm0, __shfl_xor_sync(0xffffffffu, lm0, 1));
            lm0 = fmaxf(lm0, __shfl_xor_sync(0xffffffffu, lm0, 2));
            lm1 = fmaxf(lm1, __shfl_xor_sync(0xffffffffu, lm1, 1));
            lm1 = fmaxf(lm1, __shfl_xor_sync(0xffffffffu, lm1, 2));
            if (t == 0) {
                pmax[wh * 128 + r0]     = lm0;
                pmax[wh * 128 + r0 + 8] = lm1;
            }
        }
        __syncthreads();

        if (tid < 128) {
            float mx = fmaxf(pmax[tid], pmax[128 + tid]);
            float om = rowM[tid];
            float nm = fmaxf(om, mx);
            rowM[tid]   = nm;
            alphaS[tid] = __expf(om - nm);
        }
        __syncthreads();

        // ---- P = exp(S - m), tf32-round, store + partial sums ----
        {
            float nm0 = rowM[r0], nm1 = rowM[r0 + 8];
            float ls0 = 0.0f, ls1 = 0.0f;
            #pragma unroll
            for (int nf = 0; nf < 4; nf++) {
                float p0 = to_tf32(__expf(sacc[nf][0] - nm0));
                float p1 = to_tf32(__expf(sacc[nf][1] - nm0));
                float p2 = to_tf32(__expf(sacc[nf][2] - nm1));
                float p3 = to_tf32(__expf(sacc[nf][3] - nm1));
                ls0 += p0 + p1;
                ls1 += p2 + p3;
                int n = n0w + nf * 8 + 2 * t;
                *(float2*)&Ps[r0 * 68 + n]       = make_float2(p0, p1);
                *(float2*)&Ps[(r0 + 8) * 68 + n] = make_float2(p2, p3);
            }
            ls0 += __shfl_xor_sync(0xffffffffu, ls0, 1);
            ls0 += __shfl_xor_sync(0xffffffffu, ls0, 2);
            ls1 += __shfl_xor_sync(0xffffffffu, ls1, 1);
            ls1 += __shfl_xor_sync(0xffffffffu, ls1, 2);
            if (t == 0) {
                psum[wh * 128 + r0]     = ls0;
                psum[wh * 128 + r0 + 8] = ls1;
            }
        }
        __syncthreads();

        if (tid < 128)
            rowL[tid] = rowL[tid] * alphaS[tid] + psum[tid] + psum[128 + tid];

        // ---- O = O*alpha + P Vt  (warp tile 16x128) ----
        {
            float al0 = alphaS[r0];
            float al1 = alphaS[r0 + 8];
            #pragma unroll
            for (int cf = 0; cf < 16; cf++) {
                oacc[cf][0] *= al0; oacc[cf][1] *= al0;
                oacc[cf][2] *= al1; oacc[cf][3] *= al1;
            }
        }
        const int cv0w = wh * 128;
        #pragma unroll
        for (int kn = 0; kn < 8; kn++) {
            int kc = kn * 8;
            unsigned a0 = __float_as_uint(Ps[r0 * 68 + kc + t]);
            unsigned a1 = __float_as_uint(Ps[(r0 + 8) * 68 + kc + t]);
            unsigned a2 = __float_as_uint(Ps[r0 * 68 + kc + t + 4]);
            unsigned a3 = __float_as_uint(Ps[(r0 + 8) * 68 + kc + t + 4]);
            #pragma unroll
            for (int cf = 0; cf < 16; cf++) {
                int cv = cv0w + cf * 8 + g;
                unsigned b0 = __float_as_uint(Vs[cv * 68 + kc + t]);
                unsigned b1 = __float_as_uint(Vs[cv * 68 + kc + t + 4]);
                mma_tf32(oacc[cf], a0, a1, a2, a3, b0, b1);
            }
        }
    }
    __syncthreads();

    // ---- epilogue: normalize, residual, store ----
    {
        const int cv0w = wh * 128;
        float il0 = 1.0f / rowL[r0];
        float il1 = 1.0f / rowL[r0 + 8];
        int mg = m0g + r0;
        #pragma unroll
        for (int cf = 0; cf < 16; cf++) {
            int cv = cv0w + cf * 8 + 2 * t;
            size_t i0 = ((size_t)(b * CIN + cv)) * HW + mg;
            size_t i1 = i0 + HW;
            out[i0]     = oacc[cf][0] * il0 + resid[i0];
            out[i1]     = oacc[cf][1] * il0 + resid[i1];
            out[i0 + 8] = oacc[cf][2] * il1 + resid[i0 + 8];
            out[i1 + 8] = oacc[cf][3] * il1 + resid[i1 + 8];
        }
    }
}

// ---------------------------------------------------------------------------
extern "C" void kernel_launch(void* const* d_in, const int* in_sizes, int n_in,
                              void* d_out, int out_size) {
    const float* a  = (const float*)d_in[0];
    const float* p  = (const float*)d_in[1];
    const float* Wq = (const float*)d_in[2];
    const float* bq = (const float*)d_in[3];
    const float* Wk = (const float*)d_in[4];
    const float* bk = (const float*)d_in[5];
    const float* Wv = (const float*)d_in[6];
    const float* bv = (const float*)d_in[7];
    float* out = (float*)d_out;

    float *dQ, *dK, *dV;
    cudaGetSymbolAddress((void**)&dQ, g_Q);
    cudaGetSymbolAddress((void**)&dK, g_K);
    cudaGetSymbolAddress((void**)&dV, g_V);

    dim3 blk(256);
    proj_t_kernel<<<dim3(HW / 64, CHD / 64, BB), blk>>>(Wq, bq, a, dQ, CHD);
    proj_t_kernel<<<dim3(HW / 64, CHD / 64, BB), blk>>>(Wk, bk, p, dK, CHD);
    proj_kernel  <<<dim3(HW / 64, CIN / 64, BB), blk>>>(Wv, bv, p, dV, CIN);

    const int smem = (128 * 132 + 64 * 132 + 256 * 68 + 128 * 68 + 128 * 3 + 512) * 4; // 209408
    cudaFuncSetAttribute(attn_kernel, cudaFuncAttributeMaxDynamicSharedMemorySize, smem);
    attn_kernel<<<dim3(HW / MT, BB), dim3(512), smem>>>(a, out);
}

// round 11
// speedup vs baseline: 1.8353x; 1.8353x over previous
#include <cuda_runtime.h>
#include <cstddef>

#define HW   4096
#define CIN  256
#define CHD  128
#define BB   4
#define MT   128   // query tile per CTA
#define NT   64    // key tile per iteration

// Scratch (allocation-free device globals)
__device__ float g_Q[BB * HW * CHD];   // [b][m][c]  (transposed, tf32)
__device__ float g_K[BB * HW * CHD];   // [b][n][c]  (transposed, tf32)
__device__ float g_V[BB * CIN * HW];   // [b][cv][n] (tf32)

__device__ __forceinline__ float to_tf32(float x) {
    unsigned u;
    asm("cvt.rna.tf32.f32 %0, %1;" : "=r"(u) : "f"(x));
    return __uint_as_float(u);
}

__device__ __forceinline__ void mma_tf32(float c[4],
                                         unsigned a0, unsigned a1, unsigned a2, unsigned a3,
                                         unsigned b0, unsigned b1) {
    asm volatile(
        "mma.sync.aligned.m16n8k8.row.col.f32.tf32.tf32.f32 "
        "{%0,%1,%2,%3}, {%4,%5,%6,%7}, {%8,%9}, {%0,%1,%2,%3};\n"
        : "+f"(c[0]), "+f"(c[1]), "+f"(c[2]), "+f"(c[3])
        : "r"(a0), "r"(a1), "r"(a2), "r"(a3), "r"(b0), "r"(b1));
}

__device__ __forceinline__ void ldsm_x4(unsigned& r0, unsigned& r1, unsigned& r2, unsigned& r3,
                                        unsigned addr) {
    asm volatile("ldmatrix.sync.aligned.m8n8.x4.shared.b16 {%0,%1,%2,%3}, [%4];"
                 : "=r"(r0), "=r"(r1), "=r"(r2), "=r"(r3) : "r"(addr));
}
__device__ __forceinline__ void ldsm_x2(unsigned& r0, unsigned& r1, unsigned addr) {
    asm volatile("ldmatrix.sync.aligned.m8n8.x2.shared.b16 {%0,%1}, [%2];"
                 : "=r"(r0), "=r"(r1) : "r"(addr));
}

__device__ __forceinline__ void cp_async16(unsigned dst_smem, const void* src) {
    asm volatile("cp.async.cg.shared.global [%0], [%1], 16;\n"
                 :: "r"(dst_smem), "l"(src));
}
__device__ __forceinline__ void cp_async_commit() {
    asm volatile("cp.async.commit_group;\n");
}
__device__ __forceinline__ void cp_async_wait1() {
    asm volatile("cp.async.wait_group 1;\n");
}

// ---------------------------------------------------------------------------
// V projection: Out[b, o, n] = sum_c W[o,c] X[b,c,n] + bias[o]   (tf32-rounded)
// ---------------------------------------------------------------------------
__global__ __launch_bounds__(256)
void proj_kernel(const float* __restrict__ W, const float* __restrict__ bias,
                 const float* __restrict__ X, float* __restrict__ Out, int O) {
    __shared__ float Ws[32][65];   // [k][o]
    __shared__ float Xs[32][64];   // [k][n]

    const int tid = threadIdx.x;
    const int n0  = blockIdx.x * 64;
    const int o0  = blockIdx.y * 64;
    const int b   = blockIdx.z;
    const float* Xb = X + (size_t)b * CIN * HW;

    const int tx = tid & 15;       // n quad
    const int ty = tid >> 4;       // o quad
    float acc[4][4] = {};

    for (int k0 = 0; k0 < CIN; k0 += 32) {
        {
            int r = tid >> 2;
            int q = (tid & 3) * 8;
            float4 wa = *(const float4*)&W[(size_t)(o0 + r) * CIN + k0 + q];
            float4 wb = *(const float4*)&W[(size_t)(o0 + r) * CIN + k0 + q + 4];
            Ws[q + 0][r] = wa.x; Ws[q + 1][r] = wa.y;
            Ws[q + 2][r] = wa.z; Ws[q + 3][r] = wa.w;
            Ws[q + 4][r] = wb.x; Ws[q + 5][r] = wb.y;
            Ws[q + 6][r] = wb.z; Ws[q + 7][r] = wb.w;
        }
        {
            int c  = tid >> 3;
            int nq = (tid & 7) * 8;
            const float* src = &Xb[(size_t)(k0 + c) * HW + n0 + nq];
            *(float4*)&Xs[c][nq]     = *(const float4*)&src[0];
            *(float4*)&Xs[c][nq + 4] = *(const float4*)&src[4];
        }
        __syncthreads();

        #pragma unroll
        for (int kk = 0; kk < 32; kk++) {
            float4 xv = *(float4*)&Xs[kk][tx * 4];
            float w0 = Ws[kk][ty * 4 + 0];
            float w1 = Ws[kk][ty * 4 + 1];
            float w2 = Ws[kk][ty * 4 + 2];
            float w3 = Ws[kk][ty * 4 + 3];
            acc[0][0] += w0 * xv.x; acc[0][1] += w0 * xv.y; acc[0][2] += w0 * xv.z; acc[0][3] += w0 * xv.w;
            acc[1][0] += w1 * xv.x; acc[1][1] += w1 * xv.y; acc[1][2] += w1 * xv.z; acc[1][3] += w1 * xv.w;
            acc[2][0] += w2 * xv.x; acc[2][1] += w2 * xv.y; acc[2][2] += w2 * xv.z; acc[2][3] += w2 * xv.w;
            acc[3][0] += w3 * xv.x; acc[3][1] += w3 * xv.y; acc[3][2] += w3 * xv.z; acc[3][3] += w3 * xv.w;
        }
        __syncthreads();
    }

    #pragma unroll
    for (int i = 0; i < 4; i++) {
        int o = o0 + ty * 4 + i;
        float bi = bias[o];
        float4 r;
        r.x = to_tf32(acc[i][0] + bi); r.y = to_tf32(acc[i][1] + bi);
        r.z = to_tf32(acc[i][2] + bi); r.w = to_tf32(acc[i][3] + bi);
        *(float4*)&Out[((size_t)b * O + o) * HW + n0 + tx * 4] = r;
    }
}

// ---------------------------------------------------------------------------
// Q/K projection, transposed output: Out[b, n, o] = sum_c W[o,c] X[b,c,n] + b[o]
// ---------------------------------------------------------------------------
__global__ __launch_bounds__(256)
void proj_t_kernel(const float* __restrict__ W, const float* __restrict__ bias,
                   const float* __restrict__ X, float* __restrict__ Out, int O) {
    __shared__ float Ws[32][68];   // [k][o]
    __shared__ float Xs[32][64];   // [k][n]

    const int tid = threadIdx.x;
    const int n0  = blockIdx.x * 64;
    const int o0  = blockIdx.y * 64;
    const int b   = blockIdx.z;
    const float* Xb = X + (size_t)b * CIN * HW;

    const int tx = tid & 15;       // o quad
    const int ty = tid >> 4;       // n quad
    float acc[4][4] = {};          // [n-sub][o-vec]

    for (int k0 = 0; k0 < CIN; k0 += 32) {
        {
            int r = tid >> 2;
            int q = (tid & 3) * 8;
            float4 wa = *(const float4*)&W[(size_t)(o0 + r) * CIN + k0 + q];
            float4 wb = *(const float4*)&W[(size_t)(o0 + r) * CIN + k0 + q + 4];
            Ws[q + 0][r] = wa.x; Ws[q + 1][r] = wa.y;
            Ws[q + 2][r] = wa.z; Ws[q + 3][r] = wa.w;
            Ws[q + 4][r] = wb.x; Ws[q + 5][r] = wb.y;
            Ws[q + 6][r] = wb.z; Ws[q + 7][r] = wb.w;
        }
        {
            int c  = tid >> 3;
            int nq = (tid & 7) * 8;
            const float* src = &Xb[(size_t)(k0 + c) * HW + n0 + nq];
            *(float4*)&Xs[c][nq]     = *(const float4*)&src[0];
            *(float4*)&Xs[c][nq + 4] = *(const float4*)&src[4];
        }
        __syncthreads();

        #pragma unroll
        for (int kk = 0; kk < 32; kk++) {
            float4 wv = *(float4*)&Ws[kk][tx * 4];
            float x0 = Xs[kk][ty * 4 + 0];
            float x1 = Xs[kk][ty * 4 + 1];
            float x2 = Xs[kk][ty * 4 + 2];
            float x3 = Xs[kk][ty * 4 + 3];
            acc[0][0] += x0 * wv.x; acc[0][1] += x0 * wv.y; acc[0][2] += x0 * wv.z; acc[0][3] += x0 * wv.w;
            acc[1][0] += x1 * wv.x; acc[1][1] += x1 * wv.y; acc[1][2] += x1 * wv.z; acc[1][3] += x1 * wv.w;
            acc[2][0] += x2 * wv.x; acc[2][1] += x2 * wv.y; acc[2][2] += x2 * wv.z; acc[2][3] += x2 * wv.w;
            acc[3][0] += x3 * wv.x; acc[3][1] += x3 * wv.y; acc[3][2] += x3 * wv.z; acc[3][3] += x3 * wv.w;
        }
        __syncthreads();
    }

    float4 bb = *(const float4*)&bias[o0 + tx * 4];
    #pragma unroll
    for (int i = 0; i < 4; i++) {
        int n = n0 + ty * 4 + i;
        float4 r;
        r.x = to_tf32(acc[i][0] + bb.x); r.y = to_tf32(acc[i][1] + bb.y);
        r.z = to_tf32(acc[i][2] + bb.z); r.w = to_tf32(acc[i][3] + bb.w);
        *(float4*)&Out[((size_t)b * HW + n) * O + o0 + tx * 4] = r;
    }
}

// ---------------------------------------------------------------------------
// Flash attention, tf32 mma.sync + ldmatrix + cp.async pipeline.  256 thr.
// grid (HW/128, B) = 128 CTAs (1 wave), ~205KB smem, 1 CTA/SM.
// S-phase : warps 4m x 2n, warp tile 32x32
// O-phase : warps 4m x 2cv, warp tile 32x128
// ---------------------------------------------------------------------------
__global__ __launch_bounds__(256)
void attn_kernel(const float* __restrict__ resid, float* __restrict__ out) {
    extern __shared__ float sm[];
    float* Qs     = sm;                 // [128][132]
    float* Ks     = Qs + 128 * 132;     // [64][132]
    float* Vs     = Ks + 64 * 132;      // [256][68]
    float* Ps     = Vs + 256 * 68;      // [128][68]
    float* rowM   = Ps + 128 * 68;      // 128
    float* rowL   = rowM + 128;         // 128
    float* alphaS = rowL + 128;         // 128
    float* pmax   = alphaS + 128;       // [2][128]
    float* psum   = pmax + 256;         // [2][128]

    const int tid  = threadIdx.x;
    const int b    = blockIdx.y;
    const int m0g  = blockIdx.x * MT;
    const int w    = tid >> 5;
    const int lane = tid & 31;
    const int g    = lane >> 2;
    const int t    = lane & 3;
    const int wm   = w & 3;        // m-quarter
    const int wh   = w >> 2;       // n-half (S) / cv-half (O)
    const int m0w  = wm * 32;
    const int n0w  = wh * 32;
    const int cv0w = wh * 128;

    const float* Q = g_Q + (size_t)b * HW * CHD;
    const float* K = g_K + (size_t)b * HW * CHD;
    const float* V = g_V + (size_t)b * CIN * HW;

    const unsigned qsB = (unsigned)__cvta_generic_to_shared(Qs);
    const unsigned ksB = (unsigned)__cvta_generic_to_shared(Ks);
    const unsigned vsB = (unsigned)__cvta_generic_to_shared(Vs);
    const unsigned psB = (unsigned)__cvta_generic_to_shared(Ps);

    // ldmatrix per-lane offsets (floats)
    const int l15  = lane & 15;
    const int asel = (lane >> 4) << 2;       // A col select (0 or 4)
    const int l7   = lane & 7;
    const int bsel = ((lane >> 3) & 1) << 2; // B col select (0 or 4)
    const int a_q  = (m0w + l15) * 132 + asel;   // + mf*16*132 + kc
    const int b_k  = (n0w + l7)  * 132 + bsel;   // + nf*8*132 + kc
    const int a_p  = (m0w + l15) * 68  + asel;   // + mf*16*68 + kc
    const int b_v  = (cv0w + l7) * 68  + bsel;   // + cf*8*68 + kc

    // ---- prologue: async-load Q tile + K tile 0 (one group) ----
    for (int idx = tid; idx < 128 * 32; idx += 256) {
        int r = idx >> 5, c4 = (idx & 31) << 2;
        cp_async16(qsB + (unsigned)(r * 132 + c4) * 4u, &Q[(size_t)(m0g + r) * CHD + c4]);
    }
    for (int idx = tid; idx < 64 * 32; idx += 256) {
        int r = idx >> 5, c4 = (idx & 31) << 2;
        cp_async16(ksB + (unsigned)(r * 132 + c4) * 4u, &K[(size_t)r * CHD + c4]);
    }
    cp_async_commit();
    if (tid < 128) { rowM[tid] = -1e30f; rowL[tid] = 0.0f; }

    float oacc[2][16][4];
    #pragma unroll
    for (int mf = 0; mf < 2; mf++)
        #pragma unroll
        for (int cf = 0; cf < 16; cf++)
            #pragma unroll
            for (int e = 0; e < 4; e++) oacc[mf][cf][e] = 0.0f;

    for (int nt = 0; nt < HW; nt += NT) {
        __syncthreads();   // A: prior O-phase done (Vs/Ps free)

        // B: issue V(nt) loads (overlaps S-phase)
        for (int idx = tid; idx < 256 * 16; idx += 256) {
            int r = idx >> 4, c4 = (idx & 15) << 2;
            cp_async16(vsB + (unsigned)(r * 68 + c4) * 4u, &V[(size_t)r * HW + nt + c4]);
        }
        cp_async_commit();

        cp_async_wait1();  // C: K(nt) (+Q on iter 0) complete
        __syncthreads();   // D: K visible to all

        // ---- S = Q Kt ----
        float sacc[2][4][4] = {};
        #pragma unroll
        for (int ks = 0; ks < 16; ks++) {
            int kc = ks * 8;
            unsigned a[2][4];
            ldsm_x4(a[0][0], a[0][1], a[0][2], a[0][3], qsB + (unsigned)(a_q + kc) * 4u);
            ldsm_x4(a[1][0], a[1][1], a[1][2], a[1][3], qsB + (unsigned)(a_q + 16 * 132 + kc) * 4u);
            #pragma unroll
            for (int nf = 0; nf < 4; nf++) {
                unsigned b0, b1;
                ldsm_x2(b0, b1, ksB + (unsigned)(b_k + nf * 8 * 132 + kc) * 4u);
                mma_tf32(sacc[0][nf], a[0][0], a[0][1], a[0][2], a[0][3], b0, b1);
                mma_tf32(sacc[1][nf], a[1][0], a[1][1], a[1][2], a[1][3], b0, b1);
            }
        }

        // ---- per-warp partial row max ----
        #pragma unroll
        for (int mf = 0; mf < 2; mf++) {
            int r0 = m0w + mf * 16 + g;
            float lm0 = -1e30f, lm1 = -1e30f;
            #pragma unroll
            for (int nf = 0; nf < 4; nf++) {
                lm0 = fmaxf(lm0, fmaxf(sacc[mf][nf][0], sacc[mf][nf][1]));
                lm1 = fmaxf(lm1, fmaxf(sacc[mf][nf][2], sacc[mf][nf][3]));
            }
            lm0 = fmaxf(lm0, __shfl_xor_sync(0xffffffffu, lm0, 1));
            lm0 = fmaxf(lm0, __shfl_xor_sync(0xffffffffu, lm0, 2));
            lm1 = fmaxf(lm1, __shfl_xor_sync(0xffffffffu, lm1, 1));
            lm1 = fmaxf(lm1, __shfl_xor_sync(0xffffffffu, lm1, 2));
            if (t == 0) {
                pmax[wh * 128 + r0]     = lm0;
                pmax[wh * 128 + r0 + 8] = lm1;
            }
        }
        __syncthreads();   // F1: all warps done with Ks + pmax published

        // G: prefetch K(nt+NT) into Ks (S-phase finished with it)
        {
            int ntn = (nt + NT < HW) ? nt + NT : 0;
            for (int idx = tid; idx < 64 * 32; idx += 256) {
                int r = idx >> 5, c4 = (idx & 31) << 2;
                cp_async16(ksB + (unsigned)(r * 132 + c4) * 4u,
                           &K[(size_t)(ntn + r) * CHD + c4]);
            }
            cp_async_commit();
        }

        if (tid < 128) {
            float mx = fmaxf(pmax[tid], pmax[128 + tid]);
            float om = rowM[tid];
            float nm = fmaxf(om, mx);
            rowM[tid]   = nm;
            alphaS[tid] = __expf(om - nm);
        }
        __syncthreads();   // F2: rowM/alphaS published

        // ---- P = exp(S - m), tf32-round, store + partial sums ----
        #pragma unroll
        for (int mf = 0; mf < 2; mf++) {
            int r0 = m0w + mf * 16 + g;
            float nm0 = rowM[r0], nm1 = rowM[r0 + 8];
            float ls0 = 0.0f, ls1 = 0.0f;
            #pragma unroll
            for (int nf = 0; nf < 4; nf++) {
                float p0 = to_tf32(__expf(sacc[mf][nf][0] - nm0));
                float p1 = to_tf32(__expf(sacc[mf][nf][1] - nm0));
                float p2 = to_tf32(__expf(sacc[mf][nf][2] - nm1));
                float p3 = to_tf32(__expf(sacc[mf][nf][3] - nm1));
                ls0 += p0 + p1;
                ls1 += p2 + p3;
                int n = n0w + nf * 8 + 2 * t;
                *(float2*)&Ps[r0 * 68 + n]       = make_float2(p0, p1);
                *(float2*)&Ps[(r0 + 8) * 68 + n] = make_float2(p2, p3);
            }
            ls0 += __shfl_xor_sync(0xffffffffu, ls0, 1);
            ls0 += __shfl_xor_sync(0xffffffffu, ls0, 2);
            ls1 += __shfl_xor_sync(0xffffffffu, ls1, 1);
            ls1 += __shfl_xor_sync(0xffffffffu, ls1, 2);
            if (t == 0) {
                psum[wh * 128 + r0]     = ls0;
                psum[wh * 128 + r0 + 8] = ls1;
            }
        }
        cp_async_wait1();  // V(nt) complete (K prefetch stays in flight)
        __syncthreads();   // H: Ps/psum published + Vs visible to all

        if (tid < 128)
            rowL[tid] = rowL[tid] * alphaS[tid] + psum[tid] + psum[128 + tid];

        // ---- O = O*alpha + P Vt ----
        #pragma unroll
        for (int mf = 0; mf < 2; mf++) {
            float al0 = alphaS[m0w + mf * 16 + g];
            float al1 = alphaS[m0w + mf * 16 + g + 8];
            #pragma unroll
            for (int cf = 0; cf < 16; cf++) {
                oacc[mf][cf][0] *= al0; oacc[mf][cf][1] *= al0;
                oacc[mf][cf][2] *= al1; oacc[mf][cf][3] *= al1;
            }
        }
        #pragma unroll
        for (int kn = 0; kn < 8; kn++) {
            int kc = kn * 8;
            unsigned a[2][4];
            ldsm_x4(a[0][0], a[0][1], a[0][2], a[0][3], psB + (unsigned)(a_p + kc) * 4u);
            ldsm_x4(a[1][0], a[1][1], a[1][2], a[1][3], psB + (unsigned)(a_p + 16 * 68 + kc) * 4u);
            #pragma unroll
            for (int cf = 0; cf < 16; cf++) {
                unsigned b0, b1;
                ldsm_x2(b0, b1, vsB + (unsigned)(b_v + cf * 8 * 68 + kc) * 4u);
                mma_tf32(oacc[0][cf], a[0][0], a[0][1], a[0][2], a[0][3], b0, b1);
                mma_tf32(oacc[1][cf], a[1][0], a[1][1], a[1][2], a[1][3], b0, b1);
            }
        }
    }
    __syncthreads();

    // ---- epilogue: normalize, residual, store ----
    #pragma unroll
    for (int mf = 0; mf < 2; mf++) {
        int r0 = m0w + mf * 16 + g;
        float il0 = 1.0f / rowL[r0];
        float il1 = 1.0f / rowL[r0 + 8];
        int mg = m0g + r0;
        #pragma unroll
        for (int cf = 0; cf < 16; cf++) {
            int cv = cv0w + cf * 8 + 2 * t;
            size_t i0 = ((size_t)(b * CIN + cv)) * HW + mg;
            size_t i1 = i0 + HW;
            out[i0]     = oacc[mf][cf][0] * il0 + resid[i0];
            out[i1]     = oacc[mf][cf][1] * il0 + resid[i1];
            out[i0 + 8] = oacc[mf][cf][2] * il1 + resid[i0 + 8];
            out[i1 + 8] = oacc[mf][cf][3] * il1 + resid[i1 + 8];
        }
    }
}

// ---------------------------------------------------------------------------
extern "C" void kernel_launch(void* const* d_in, const int* in_sizes, int n_in,
                              void* d_out, int out_size) {
    const float* a  = (const float*)d_in[0];
    const float* p  = (const float*)d_in[1];
    const float* Wq = (const float*)d_in[2];
    const float* bq = (const float*)d_in[3];
    const float* Wk = (const float*)d_in[4];
    const float* bk = (const float*)d_in[5];
    const float* Wv = (const float*)d_in[6];
    const float* bv = (const float*)d_in[7];
    float* out = (float*)d_out;

    float *dQ, *dK, *dV;
    cudaGetSymbolAddress((void**)&dQ, g_Q);
    cudaGetSymbolAddress((void**)&dK, g_K);
    cudaGetSymbolAddress((void**)&dV, g_V);

    dim3 blk(256);
    proj_t_kernel<<<dim3(HW / 64, CHD / 64, BB), blk>>>(Wq, bq, a, dQ, CHD);
    proj_t_kernel<<<dim3(HW / 64, CHD / 64, BB), blk>>>(Wk, bk, p, dK, CHD);
    proj_kernel  <<<dim3(HW / 64, CIN / 64, BB), blk>>>(Wv, bv, p, dV, CIN);

    const int smem = (128 * 132 + 64 * 132 + 256 * 68 + 128 * 68 + 128 * 3 + 512) * 4; // 209408
    cudaFuncSetAttribute(attn_kernel, cudaFuncAttributeMaxDynamicSharedMemorySize, smem);
    attn_kernel<<<dim3(HW / MT, BB), blk, smem>>>(a, out);
}

// round 13
// speedup vs baseline: 1.8966x; 1.0334x over previous
#include <cuda_runtime.h>
#include <cstddef>

#define HW   4096
#define CIN  256
#define CHD  128
#define BB   4
#define MT   128   // query tile per CTA
#define NT   64    // key tile per iteration

// Scratch (allocation-free device globals)
__device__ float g_Q[BB * HW * CHD];   // [b][m][c]  (transposed, tf32)
__device__ float g_K[BB * HW * CHD];   // [b][n][c]  (transposed, tf32)
__device__ float g_V[BB * CIN * HW];   // [b][cv][n] (tf32)

__device__ __forceinline__ float to_tf32(float x) {
    unsigned u;
    asm("cvt.rna.tf32.f32 %0, %1;" : "=r"(u) : "f"(x));
    return __uint_as_float(u);
}

__device__ __forceinline__ void mma_tf32(float c[4],
                                         unsigned a0, unsigned a1, unsigned a2, unsigned a3,
                                         unsigned b0, unsigned b1) {
    asm volatile(
        "mma.sync.aligned.m16n8k8.row.col.f32.tf32.tf32.f32 "
        "{%0,%1,%2,%3}, {%4,%5,%6,%7}, {%8,%9}, {%0,%1,%2,%3};\n"
        : "+f"(c[0]), "+f"(c[1]), "+f"(c[2]), "+f"(c[3])
        : "r"(a0), "r"(a1), "r"(a2), "r"(a3), "r"(b0), "r"(b1));
}

__device__ __forceinline__ void ldsm_x4(unsigned& r0, unsigned& r1, unsigned& r2, unsigned& r3,
                                        unsigned addr) {
    asm volatile("ldmatrix.sync.aligned.m8n8.x4.shared.b16 {%0,%1,%2,%3}, [%4];"
                 : "=r"(r0), "=r"(r1), "=r"(r2), "=r"(r3) : "r"(addr));
}

__device__ __forceinline__ void cp_async16(unsigned dst_smem, const void* src) {
    asm volatile("cp.async.cg.shared.global [%0], [%1], 16;\n"
                 :: "r"(dst_smem), "l"(src));
}
__device__ __forceinline__ void cp_async_commit() {
    asm volatile("cp.async.commit_group;\n");
}
__device__ __forceinline__ void cp_async_wait1() {
    asm volatile("cp.async.wait_group 1;\n");
}

// ---------------------------------------------------------------------------
// V projection: Out[b, o, n] = sum_c W[o,c] X[b,c,n] + bias[o]   (tf32-rounded)
// ---------------------------------------------------------------------------
__global__ __launch_bounds__(256)
void proj_kernel(const float* __restrict__ W, const float* __restrict__ bias,
                 const float* __restrict__ X, float* __restrict__ Out, int O) {
    __shared__ float Ws[32][65];   // [k][o]
    __shared__ float Xs[32][64];   // [k][n]

    const int tid = threadIdx.x;
    const int n0  = blockIdx.x * 64;
    const int o0  = blockIdx.y * 64;
    const int b   = blockIdx.z;
    const float* Xb = X + (size_t)b * CIN * HW;

    const int tx = tid & 15;       // n quad
    const int ty = tid >> 4;       // o quad
    float acc[4][4] = {};

    for (int k0 = 0; k0 < CIN; k0 += 32) {
        {
            int r = tid >> 2;
            int q = (tid & 3) * 8;
            float4 wa = *(const float4*)&W[(size_t)(o0 + r) * CIN + k0 + q];
            float4 wb = *(const float4*)&W[(size_t)(o0 + r) * CIN + k0 + q + 4];
            Ws[q + 0][r] = wa.x; Ws[q + 1][r] = wa.y;
            Ws[q + 2][r] = wa.z; Ws[q + 3][r] = wa.w;
            Ws[q + 4][r] = wb.x; Ws[q + 5][r] = wb.y;
            Ws[q + 6][r] = wb.z; Ws[q + 7][r] = wb.w;
        }
        {
            int c  = tid >> 3;
            int nq = (tid & 7) * 8;
            const float* src = &Xb[(size_t)(k0 + c) * HW + n0 + nq];
            *(float4*)&Xs[c][nq]     = *(const float4*)&src[0];
            *(float4*)&Xs[c][nq + 4] = *(const float4*)&src[4];
        }
        __syncthreads();

        #pragma unroll
        for (int kk = 0; kk < 32; kk++) {
            float4 xv = *(float4*)&Xs[kk][tx * 4];
            float w0 = Ws[kk][ty * 4 + 0];
            float w1 = Ws[kk][ty * 4 + 1];
            float w2 = Ws[kk][ty * 4 + 2];
            float w3 = Ws[kk][ty * 4 + 3];
            acc[0][0] += w0 * xv.x; acc[0][1] += w0 * xv.y; acc[0][2] += w0 * xv.z; acc[0][3] += w0 * xv.w;
            acc[1][0] += w1 * xv.x; acc[1][1] += w1 * xv.y; acc[1][2] += w1 * xv.z; acc[1][3] += w1 * xv.w;
            acc[2][0] += w2 * xv.x; acc[2][1] += w2 * xv.y; acc[2][2] += w2 * xv.z; acc[2][3] += w2 * xv.w;
            acc[3][0] += w3 * xv.x; acc[3][1] += w3 * xv.y; acc[3][2] += w3 * xv.z; acc[3][3] += w3 * xv.w;
        }
        __syncthreads();
    }

    #pragma unroll
    for (int i = 0; i < 4; i++) {
        int o = o0 + ty * 4 + i;
        float bi = bias[o];
        float4 r;
        r.x = to_tf32(acc[i][0] + bi); r.y = to_tf32(acc[i][1] + bi);
        r.z = to_tf32(acc[i][2] + bi); r.w = to_tf32(acc[i][3] + bi);
        *(float4*)&Out[((size_t)b * O + o) * HW + n0 + tx * 4] = r;
    }
}

// ---------------------------------------------------------------------------
// Q/K projection, transposed output: Out[b, n, o] = sum_c W[o,c] X[b,c,n] + b[o]
// ---------------------------------------------------------------------------
__global__ __launch_bounds__(256)
void proj_t_kernel(const float* __restrict__ W, const float* __restrict__ bias,
                   const float* __restrict__ X, float* __restrict__ Out, int O) {
    __shared__ float Ws[32][68];   // [k][o]
    __shared__ float Xs[32][64];   // [k][n]

    const int tid = threadIdx.x;
    const int n0  = blockIdx.x * 64;
    const int o0  = blockIdx.y * 64;
    const int b   = blockIdx.z;
    const float* Xb = X + (size_t)b * CIN * HW;

    const int tx = tid & 15;       // o quad
    const int ty = tid >> 4;       // n quad
    float acc[4][4] = {};          // [n-sub][o-vec]

    for (int k0 = 0; k0 < CIN; k0 += 32) {
        {
            int r = tid >> 2;
            int q = (tid & 3) * 8;
            float4 wa = *(const float4*)&W[(size_t)(o0 + r) * CIN + k0 + q];
            float4 wb = *(const float4*)&W[(size_t)(o0 + r) * CIN + k0 + q + 4];
            Ws[q + 0][r] = wa.x; Ws[q + 1][r] = wa.y;
            Ws[q + 2][r] = wa.z; Ws[q + 3][r] = wa.w;
            Ws[q + 4][r] = wb.x; Ws[q + 5][r] = wb.y;
            Ws[q + 6][r] = wb.z; Ws[q + 7][r] = wb.w;
        }
        {
            int c  = tid >> 3;
            int nq = (tid & 7) * 8;
            const float* src = &Xb[(size_t)(k0 + c) * HW + n0 + nq];
            *(float4*)&Xs[c][nq]     = *(const float4*)&src[0];
            *(float4*)&Xs[c][nq + 4] = *(const float4*)&src[4];
        }
        __syncthreads();

        #pragma unroll
        for (int kk = 0; kk < 32; kk++) {
            float4 wv = *(float4*)&Ws[kk][tx * 4];
            float x0 = Xs[kk][ty * 4 + 0];
            float x1 = Xs[kk][ty * 4 + 1];
            float x2 = Xs[kk][ty * 4 + 2];
            float x3 = Xs[kk][ty * 4 + 3];
            acc[0][0] += x0 * wv.x; acc[0][1] += x0 * wv.y; acc[0][2] += x0 * wv.z; acc[0][3] += x0 * wv.w;
            acc[1][0] += x1 * wv.x; acc[1][1] += x1 * wv.y; acc[1][2] += x1 * wv.z; acc[1][3] += x1 * wv.w;
            acc[2][0] += x2 * wv.x; acc[2][1] += x2 * wv.y; acc[2][2] += x2 * wv.z; acc[2][3] += x2 * wv.w;
            acc[3][0] += x3 * wv.x; acc[3][1] += x3 * wv.y; acc[3][2] += x3 * wv.z; acc[3][3] += x3 * wv.w;
        }
        __syncthreads();
    }

    float4 bb = *(const float4*)&bias[o0 + tx * 4];
    #pragma unroll
    for (int i = 0; i < 4; i++) {
        int n = n0 + ty * 4 + i;
        float4 r;
        r.x = to_tf32(acc[i][0] + bb.x); r.y = to_tf32(acc[i][1] + bb.y);
        r.z = to_tf32(acc[i][2] + bb.z); r.w = to_tf32(acc[i][3] + bb.w);
        *(float4*)&Out[((size_t)b * HW + n) * O + o0 + tx * 4] = r;
    }
}

// ---------------------------------------------------------------------------
// Flash attention, tf32 mma.sync + ldmatrix(x4) + cp.async pipeline. 256 thr.
// grid (HW/128, B) = 128 CTAs (1 wave), ~208KB smem, 1 CTA/SM.
// S-phase : warps 4m x 2n, warp tile 32x32
// O-phase : warps 4m x 2cv, warp tile 32x128  (same m rows as S-phase!)
// Softmax state (rowM/rowL/alpha) register-resident; only cross-half partial
// max/sum go through smem (pmax/psum).
// ---------------------------------------------------------------------------
__global__ __launch_bounds__(256)
void attn_kernel(const float* __restrict__ resid, float* __restrict__ out) {
    extern __shared__ float sm[];
    float* Qs   = sm;                 // [128][132]
    float* Ks   = Qs + 128 * 132;     // [64][132]
    float* Vs   = Ks + 64 * 132;      // [256][68]
    float* Ps   = Vs + 256 * 68;      // [128][68]
    float* pmax = Ps + 128 * 68;      // [2][128]
    float* psum = pmax + 256;         // [2][128]

    const int tid  = threadIdx.x;
    const int b    = blockIdx.y;
    const int m0g  = blockIdx.x * MT;
    const int w    = tid >> 5;
    const int lane = tid & 31;
    const int g    = lane >> 2;
    const int t    = lane & 3;
    const int wm   = w & 3;        // m-quarter
    const int wh   = w >> 2;       // n-half (S) / cv-half (O)
    const int m0w  = wm * 32;
    const int n0w  = wh * 32;
    const int cv0w = wh * 128;

    const float* Q = g_Q + (size_t)b * HW * CHD;
    const float* K = g_K + (size_t)b * HW * CHD;
    const float* V = g_V + (size_t)b * CIN * HW;

    const unsigned qsB = (unsigned)__cvta_generic_to_shared(Qs);
    const unsigned ksB = (unsigned)__cvta_generic_to_shared(Ks);
    const unsigned vsB = (unsigned)__cvta_generic_to_shared(Vs);
    const unsigned psB = (unsigned)__cvta_generic_to_shared(Ps);

    // ldmatrix per-lane offsets (floats)
    const int l15   = lane & 15;
    const int asel  = (lane >> 4) << 2;            // A col select (0 or 4)
    const int brow4 = (lane & 7) + ((lane >> 4) << 3);   // x4-B row within 16
    const int bsel4 = ((lane >> 3) & 1) << 2;            // x4-B col select
    const int a_q  = (m0w + l15) * 132 + asel;           // + mf*16*132 + kc
    const int b_k4 = (n0w + brow4) * 132 + bsel4;        // + nfp*16*132 + kc
    const int a_p  = (m0w + l15) * 68 + asel;            // + mf*16*68 + kc
    const int b_v4 = (cv0w + brow4) * 68 + bsel4;        // + cfp*16*68 + kc

    // ---- prologue: async-load Q tile + K tile 0 (one group) ----
    for (int idx = tid; idx < 128 * 32; idx += 256) {
        int r = idx >> 5, c4 = (idx & 31) << 2;
        cp_async16(qsB + (unsigned)(r * 132 + c4) * 4u, &Q[(size_t)(m0g + r) * CHD + c4]);
    }
    for (int idx = tid; idx < 64 * 32; idx += 256) {
        int r = idx >> 5, c4 = (idx & 31) << 2;
        cp_async16(ksB + (unsigned)(r * 132 + c4) * 4u, &K[(size_t)r * CHD + c4]);
    }
    cp_async_commit();

    // Register-resident softmax state: rows (m0w + mf*16 + g) and (+8)
    float rowM[2][2], rowL[2][2], alpha[2][2];
    #pragma unroll
    for (int mf = 0; mf < 2; mf++) {
        rowM[mf][0] = -1e30f; rowM[mf][1] = -1e30f;
        rowL[mf][0] = 0.0f;   rowL[mf][1] = 0.0f;
    }

    float oacc[2][16][4];
    #pragma unroll
    for (int mf = 0; mf < 2; mf++)
        #pragma unroll
        for (int cf = 0; cf < 16; cf++)
            #pragma unroll
            for (int e = 0; e < 4; e++) oacc[mf][cf][e] = 0.0f;

    for (int nt = 0; nt < HW; nt += NT) {
        __syncthreads();   // A: prior O-phase done (Vs/Ps free)

        // issue V(nt) loads (overlaps S-phase)
        for (int idx = tid; idx < 256 * 16; idx += 256) {
            int r = idx >> 4, c4 = (idx & 15) << 2;
            cp_async16(vsB + (unsigned)(r * 68 + c4) * 4u, &V[(size_t)r * HW + nt + c4]);
        }
        cp_async_commit();

        cp_async_wait1();  // K(nt) (+Q on iter 0) complete
        __syncthreads();   // D: K visible to all

        // ---- S = Q Kt ----
        float sacc[2][4][4] = {};
        #pragma unroll
        for (int ks = 0; ks < 16; ks++) {
            int kc = ks * 8;
            unsigned a[2][4];
            ldsm_x4(a[0][0], a[0][1], a[0][2], a[0][3], qsB + (unsigned)(a_q + kc) * 4u);
            ldsm_x4(a[1][0], a[1][1], a[1][2], a[1][3], qsB + (unsigned)(a_q + 16 * 132 + kc) * 4u);
            #pragma unroll
            for (int nfp = 0; nfp < 2; nfp++) {
                unsigned b0, b1, b2, b3;
                ldsm_x4(b0, b1, b2, b3, ksB + (unsigned)(b_k4 + nfp * 16 * 132 + kc) * 4u);
                mma_tf32(sacc[0][2 * nfp],     a[0][0], a[0][1], a[0][2], a[0][3], b0, b1);
                mma_tf32(sacc[1][2 * nfp],     a[1][0], a[1][1], a[1][2], a[1][3], b0, b1);
                mma_tf32(sacc[0][2 * nfp + 1], a[0][0], a[0][1], a[0][2], a[0][3], b2, b3);
                mma_tf32(sacc[1][2 * nfp + 1], a[1][0], a[1][1], a[1][2], a[1][3], b2, b3);
            }
        }

        // ---- per-warp partial row max (kept in regs, published per-half) ----
        float lm[2][2];
        #pragma unroll
        for (int mf = 0; mf < 2; mf++) {
            float lm0 = -1e30f, lm1 = -1e30f;
            #pragma unroll
            for (int nf = 0; nf < 4; nf++) {
                lm0 = fmaxf(lm0, fmaxf(sacc[mf][nf][0], sacc[mf][nf][1]));
                lm1 = fmaxf(lm1, fmaxf(sacc[mf][nf][2], sacc[mf][nf][3]));
            }
            lm0 = fmaxf(lm0, __shfl_xor_sync(0xffffffffu, lm0, 1));
            lm0 = fmaxf(lm0, __shfl_xor_sync(0xffffffffu, lm0, 2));
            lm1 = fmaxf(lm1, __shfl_xor_sync(0xffffffffu, lm1, 1));
            lm1 = fmaxf(lm1, __shfl_xor_sync(0xffffffffu, lm1, 2));
            lm[mf][0] = lm0; lm[mf][1] = lm1;
            if (t == 0) {
                pmax[wh * 128 + m0w + mf * 16 + g]     = lm0;
                pmax[wh * 128 + m0w + mf * 16 + g + 8] = lm1;
            }
        }
        __syncthreads();   // F1: Ks consumed + pmax published

        // prefetch K(nt+NT) into Ks (S-phase finished with it)
        {
            int ntn = (nt + NT < HW) ? nt + NT : 0;
            for (int idx = tid; idx < 64 * 32; idx += 256) {
                int r = idx >> 5, c4 = (idx & 31) << 2;
                cp_async16(ksB + (unsigned)(r * 132 + c4) * 4u,
                           &K[(size_t)(ntn + r) * CHD + c4]);
            }
            cp_async_commit();
        }

        // ---- finalize rowM/alpha in registers (no serialized block) ----
        const float* pmaxO = pmax + (wh ^ 1) * 128;
        #pragma unroll
        for (int mf = 0; mf < 2; mf++) {
            int r0 = m0w + mf * 16 + g;
            float nm0 = fmaxf(rowM[mf][0], fmaxf(lm[mf][0], pmaxO[r0]));
            float nm1 = fmaxf(rowM[mf][1], fmaxf(lm[mf][1], pmaxO[r0 + 8]));
            alpha[mf][0] = __expf(rowM[mf][0] - nm0);
            alpha[mf][1] = __expf(rowM[mf][1] - nm1);
            rowM[mf][0] = nm0; rowM[mf][1] = nm1;
        }

        // ---- P = exp(S - m), tf32-round, store + partial sums ----
        float ls[2][2];
        #pragma unroll
        for (int mf = 0; mf < 2; mf++) {
            int r0 = m0w + mf * 16 + g;
            float nm0 = rowM[mf][0], nm1 = rowM[mf][1];
            float ls0 = 0.0f, ls1 = 0.0f;
            #pragma unroll
            for (int nf = 0; nf < 4; nf++) {
                float p0 = to_tf32(__expf(sacc[mf][nf][0] - nm0));
                float p1 = to_tf32(__expf(sacc[mf][nf][1] - nm0));
                float p2 = to_tf32(__expf(sacc[mf][nf][2] - nm1));
                float p3 = to_tf32(__expf(sacc[mf][nf][3] - nm1));
                ls0 += p0 + p1;
                ls1 += p2 + p3;
                int n = n0w + nf * 8 + 2 * t;
                *(float2*)&Ps[r0 * 68 + n]       = make_float2(p0, p1);
                *(float2*)&Ps[(r0 + 8) * 68 + n] = make_float2(p2, p3);
            }
            ls0 += __shfl_xor_sync(0xffffffffu, ls0, 1);
            ls0 += __shfl_xor_sync(0xffffffffu, ls0, 2);
            ls1 += __shfl_xor_sync(0xffffffffu, ls1, 1);
            ls1 += __shfl_xor_sync(0xffffffffu, ls1, 2);
            ls[mf][0] = ls0; ls[mf][1] = ls1;
            if (t == 0) {
                psum[wh * 128 + r0]     = ls0;
                psum[wh * 128 + r0 + 8] = ls1;
            }
        }
        cp_async_wait1();  // V(nt) complete (K prefetch stays in flight)
        __syncthreads();   // H: Ps/psum published + Vs visible to all

        // ---- rowL update in registers ----
        const float* psumO = psum + (wh ^ 1) * 128;
        #pragma unroll
        for (int mf = 0; mf < 2; mf++) {
            int r0 = m0w + mf * 16 + g;
            rowL[mf][0] = rowL[mf][0] * alpha[mf][0] + ls[mf][0] + psumO[r0];
            rowL[mf][1] = rowL[mf][1] * alpha[mf][1] + ls[mf][1] + psumO[r0 + 8];
        }

        // ---- O = O*alpha + P Vt ----
        #pragma unroll
        for (int mf = 0; mf < 2; mf++) {
            float al0 = alpha[mf][0];
            float al1 = alpha[mf][1];
            #pragma unroll
            for (int cf = 0; cf < 16; cf++) {
                oacc[mf][cf][0] *= al0; oacc[mf][cf][1] *= al0;
                oacc[mf][cf][2] *= al1; oacc[mf][cf][3] *= al1;
            }
        }
        #pragma unroll
        for (int kn = 0; kn < 8; kn++) {
            int kc = kn * 8;
            unsigned a[2][4];
            ldsm_x4(a[0][0], a[0][1], a[0][2], a[0][3], psB + (unsigned)(a_p + kc) * 4u);
            ldsm_x4(a[1][0], a[1][1], a[1][2], a[1][3], psB + (unsigned)(a_p + 16 * 68 + kc) * 4u);
            #pragma unroll
            for (int cfp = 0; cfp < 8; cfp++) {
                unsigned b0, b1, b2, b3;
                ldsm_x4(b0, b1, b2, b3, vsB + (unsigned)(b_v4 + cfp * 16 * 68 + kc) * 4u);
                mma_tf32(oacc[0][2 * cfp],     a[0][0], a[0][1], a[0][2], a[0][3], b0, b1);
                mma_tf32(oacc[1][2 * cfp],     a[1][0], a[1][1], a[1][2], a[1][3], b0, b1);
                mma_tf32(oacc[0][2 * cfp + 1], a[0][0], a[0][1], a[0][2], a[0][3], b2, b3);
                mma_tf32(oacc[1][2 * cfp + 1], a[1][0], a[1][1], a[1][2], a[1][3], b2, b3);
            }
        }
    }

    // ---- epilogue: normalize (register rowL), residual, store ----
    #pragma unroll
    for (int mf = 0; mf < 2; mf++) {
        int r0 = m0w + mf * 16 + g;
        float il0 = 1.0f / rowL[mf][0];
        float il1 = 1.0f / rowL[mf][1];
        int mg = m0g + r0;
        #pragma unroll
        for (int cf = 0; cf < 16; cf++) {
            int cv = cv0w + cf * 8 + 2 * t;
            size_t i0 = ((size_t)(b * CIN + cv)) * HW + mg;
            size_t i1 = i0 + HW;
            out[i0]     = oacc[mf][cf][0] * il0 + resid[i0];
            out[i1]     = oacc[mf][cf][1] * il0 + resid[i1];
            out[i0 + 8] = oacc[mf][cf][2] * il1 + resid[i0 + 8];
            out[i1 + 8] = oacc[mf][cf][3] * il1 + resid[i1 + 8];
        }
    }
}

// ---------------------------------------------------------------------------
extern "C" void kernel_launch(void* const* d_in, const int* in_sizes, int n_in,
                              void* d_out, int out_size) {
    const float* a  = (const float*)d_in[0];
    const float* p  = (const float*)d_in[1];
    const float* Wq = (const float*)d_in[2];
    const float* bq = (const float*)d_in[3];
    const float* Wk = (const float*)d_in[4];
    const float* bk = (const float*)d_in[5];
    const float* Wv = (const float*)d_in[6];
    const float* bv = (const float*)d_in[7];
    float* out = (float*)d_out;

    float *dQ, *dK, *dV;
    cudaGetSymbolAddress((void**)&dQ, g_Q);
    cudaGetSymbolAddress((void**)&dK, g_K);
    cudaGetSymbolAddress((void**)&dV, g_V);

    dim3 blk(256);
    proj_t_kernel<<<dim3(HW / 64, CHD / 64, BB), blk>>>(Wq, bq, a, dQ, CHD);
    proj_t_kernel<<<dim3(HW / 64, CHD / 64, BB), blk>>>(Wk, bk, p, dK, CHD);
    proj_kernel  <<<dim3(HW / 64, CIN / 64, BB), blk>>>(Wv, bv, p, dV, CIN);

    const int smem = (128 * 132 + 64 * 132 + 256 * 68 + 128 * 68 + 512) * 4; // 207872
    cudaFuncSetAttribute(attn_kernel, cudaFuncAttributeMaxDynamicSharedMemorySize, smem);
    attn_kernel<<<dim3(HW / MT, BB), blk, smem>>>(a, out);
}

// round 16
// speedup vs baseline: 2.6914x; 1.4190x over previous
#include <cuda_runtime.h>
#include <cuda_fp16.h>
#include <cstddef>

#define HW   4096
#define CIN  256
#define CHD  128
#define BB   4
#define MT   128   // query tile per CTA
#define NT   64    // key tile per iteration

// Scratch (allocation-free device globals) — fp16 storage
__device__ __half g_Q[BB * HW * CHD];   // [b][m][c]
__device__ __half g_K[BB * HW * CHD];   // [b][n][c]
__device__ __half g_V[BB * CIN * HW];   // [b][cv][n]

__device__ __forceinline__ void mma_f16(float c[4],
                                        unsigned a0, unsigned a1, unsigned a2, unsigned a3,
                                        unsigned b0, unsigned b1) {
    asm volatile(
        "mma.sync.aligned.m16n8k16.row.col.f32.f16.f16.f32 "
        "{%0,%1,%2,%3}, {%4,%5,%6,%7}, {%8,%9}, {%0,%1,%2,%3};\n"
        : "+f"(c[0]), "+f"(c[1]), "+f"(c[2]), "+f"(c[3])
        : "r"(a0), "r"(a1), "r"(a2), "r"(a3), "r"(b0), "r"(b1));
}

__device__ __forceinline__ void ldsm_x4(unsigned& r0, unsigned& r1, unsigned& r2, unsigned& r3,
                                        unsigned addr) {
    asm volatile("ldmatrix.sync.aligned.m8n8.x4.shared.b16 {%0,%1,%2,%3}, [%4];"
                 : "=r"(r0), "=r"(r1), "=r"(r2), "=r"(r3) : "r"(addr));
}

__device__ __forceinline__ void cp_async16(unsigned dst_smem, const void* src) {
    asm volatile("cp.async.cg.shared.global [%0], [%1], 16;\n"
                 :: "r"(dst_smem), "l"(src));
}
__device__ __forceinline__ void cp_async_commit() {
    asm volatile("cp.async.commit_group;\n");
}
__device__ __forceinline__ void cp_async_wait1() {
    asm volatile("cp.async.wait_group 1;\n");
}

// ---------------------------------------------------------------------------
// V projection: Out[b, o, n] = sum_c W[o,c] X[b,c,n] + bias[o]   (fp16 out)
// ---------------------------------------------------------------------------
__global__ __launch_bounds__(256)
void proj_kernel(const float* __restrict__ W, const float* __restrict__ bias,
                 const float* __restrict__ X, __half* __restrict__ Out, int O) {
    __shared__ float Ws[32][65];   // [k][o]
    __shared__ float Xs[32][64];   // [k][n]

    const int tid = threadIdx.x;
    const int n0  = blockIdx.x * 64;
    const int o0  = blockIdx.y * 64;
    const int b   = blockIdx.z;
    const float* Xb = X + (size_t)b * CIN * HW;

    const int tx = tid & 15;       // n quad
    const int ty = tid >> 4;       // o quad
    float acc[4][4] = {};

    for (int k0 = 0; k0 < CIN; k0 += 32) {
        {
            int r = tid >> 2;
            int q = (tid & 3) * 8;
            float4 wa = *(const float4*)&W[(size_t)(o0 + r) * CIN + k0 + q];
            float4 wb = *(const float4*)&W[(size_t)(o0 + r) * CIN + k0 + q + 4];
            Ws[q + 0][r] = wa.x; Ws[q + 1][r] = wa.y;
            Ws[q + 2][r] = wa.z; Ws[q + 3][r] = wa.w;
            Ws[q + 4][r] = wb.x; Ws[q + 5][r] = wb.y;
            Ws[q + 6][r] = wb.z; Ws[q + 7][r] = wb.w;
        }
        {
            int c  = tid >> 3;
            int nq = (tid & 7) * 8;
            const float* src = &Xb[(size_t)(k0 + c) * HW + n0 + nq];
            *(float4*)&Xs[c][nq]     = *(const float4*)&src[0];
            *(float4*)&Xs[c][nq + 4] = *(const float4*)&src[4];
        }
        __syncthreads();

        #pragma unroll
        for (int kk = 0; kk < 32; kk++) {
            float4 xv = *(float4*)&Xs[kk][tx * 4];
            float w0 = Ws[kk][ty * 4 + 0];
            float w1 = Ws[kk][ty * 4 + 1];
            float w2 = Ws[kk][ty * 4 + 2];
            float w3 = Ws[kk][ty * 4 + 3];
            acc[0][0] += w0 * xv.x; acc[0][1] += w0 * xv.y; acc[0][2] += w0 * xv.z; acc[0][3] += w0 * xv.w;
            acc[1][0] += w1 * xv.x; acc[1][1] += w1 * xv.y; acc[1][2] += w1 * xv.z; acc[1][3] += w1 * xv.w;
            acc[2][0] += w2 * xv.x; acc[2][1] += w2 * xv.y; acc[2][2] += w2 * xv.z; acc[2][3] += w2 * xv.w;
            acc[3][0] += w3 * xv.x; acc[3][1] += w3 * xv.y; acc[3][2] += w3 * xv.z; acc[3][3] += w3 * xv.w;
        }
        __syncthreads();
    }

    #pragma unroll
    for (int i = 0; i < 4; i++) {
        int o = o0 + ty * 4 + i;
        float bi = bias[o];
        __half2 hv[2];
        hv[0] = __floats2half2_rn(acc[i][0] + bi, acc[i][1] + bi);
        hv[1] = __floats2half2_rn(acc[i][2] + bi, acc[i][3] + bi);
        *(uint2*)&Out[((size_t)b * O + o) * HW + n0 + tx * 4] = *(uint2*)hv;
    }
}

// ---------------------------------------------------------------------------
// Q/K projection, transposed fp16 output: Out[b, n, o] = sum_c W[o,c] X[b,c,n] + b[o]
// ---------------------------------------------------------------------------
__global__ __launch_bounds__(256)
void proj_t_kernel(const float* __restrict__ W, const float* __restrict__ bias,
                   const float* __restrict__ X, __half* __restrict__ Out, int O) {
    __shared__ float Ws[32][68];   // [k][o]
    __shared__ float Xs[32][64];   // [k][n]

    const int tid = threadIdx.x;
    const int n0  = blockIdx.x * 64;
    const int o0  = blockIdx.y * 64;
    const int b   = blockIdx.z;
    const float* Xb = X + (size_t)b * CIN * HW;

    const int tx = tid & 15;       // o quad
    const int ty = tid >> 4;       // n quad
    float acc[4][4] = {};          // [n-sub][o-vec]

    for (int k0 = 0; k0 < CIN; k0 += 32) {
        {
            int r = tid >> 2;
            int q = (tid & 3) * 8;
            float4 wa = *(const float4*)&W[(size_t)(o0 + r) * CIN + k0 + q];
            float4 wb = *(const float4*)&W[(size_t)(o0 + r) * CIN + k0 + q + 4];
            Ws[q + 0][r] = wa.x; Ws[q + 1][r] = wa.y;
            Ws[q + 2][r] = wa.z; Ws[q + 3][r] = wa.w;
            Ws[q + 4][r] = wb.x; Ws[q + 5][r] = wb.y;
            Ws[q + 6][r] = wb.z; Ws[q + 7][r] = wb.w;
        }
        {
            int c  = tid >> 3;
            int nq = (tid & 7) * 8;
            const float* src = &Xb[(size_t)(k0 + c) * HW + n0 + nq];
            *(float4*)&Xs[c][nq]     = *(const float4*)&src[0];
            *(float4*)&Xs[c][nq + 4] = *(const float4*)&src[4];
        }
        __syncthreads();

        #pragma unroll
        for (int kk = 0; kk < 32; kk++) {
            float4 wv = *(float4*)&Ws[kk][tx * 4];
            float x0 = Xs[kk][ty * 4 + 0];
            float x1 = Xs[kk][ty * 4 + 1];
            float x2 = Xs[kk][ty * 4 + 2];
            float x3 = Xs[kk][ty * 4 + 3];
            acc[0][0] += x0 * wv.x; acc[0][1] += x0 * wv.y; acc[0][2] += x0 * wv.z; acc[0][3] += x0 * wv.w;
            acc[1][0] += x1 * wv.x; acc[1][1] += x1 * wv.y; acc[1][2] += x1 * wv.z; acc[1][3] += x1 * wv.w;
            acc[2][0] += x2 * wv.x; acc[2][1] += x2 * wv.y; acc[2][2] += x2 * wv.z; acc[2][3] += x2 * wv.w;
            acc[3][0] += x3 * wv.x; acc[3][1] += x3 * wv.y; acc[3][2] += x3 * wv.z; acc[3][3] += x3 * wv.w;
        }
        __syncthreads();
    }

    float4 bb = *(const float4*)&bias[o0 + tx * 4];
    #pragma unroll
    for (int i = 0; i < 4; i++) {
        int n = n0 + ty * 4 + i;
        __half2 hv[2];
        hv[0] = __floats2half2_rn(acc[i][0] + bb.x, acc[i][1] + bb.y);
        hv[1] = __floats2half2_rn(acc[i][2] + bb.z, acc[i][3] + bb.w);
        *(uint2*)&Out[((size_t)b * HW + n) * O + o0 + tx * 4] = *(uint2*)hv;
    }
}

// ---------------------------------------------------------------------------
// Flash attention, fp16 mma.sync m16n8k16 + ldmatrix(x4) + cp.async. 256 thr.
// grid (HW/128, B) = 128 CTAs (1 wave), ~107KB smem.
// S-phase : warps 4m x 2n, warp tile 32x32, K=128 -> 8 ksteps
// O-phase : warps 4m x 2cv, warp tile 32x128, K=64 -> 4 ksteps
// Softmax state register-resident; cross-half partials via smem.
// ---------------------------------------------------------------------------
#define QS_STR 136   // 128 + 8 halfs pad (16B)  -> conflict-free ldmatrix
#define VS_STR 72    // 64 + 8 halfs pad

__global__ __launch_bounds__(256)
void attn_kernel(const float* __restrict__ resid, float* __restrict__ out) {
    extern __shared__ __half smh[];
    __half* Qs  = smh;                  // [128][136]
    __half* Ks  = Qs + 128 * QS_STR;    // [64][136]
    __half* Vs  = Ks + 64 * QS_STR;     // [256][72]
    __half* Ps  = Vs + 256 * VS_STR;    // [128][72]
    float* pmax = (float*)(Ps + 128 * VS_STR);  // [2][128]
    float* psum = pmax + 256;                   // [2][128]

    const int tid  = threadIdx.x;
    const int b    = blockIdx.y;
    const int m0g  = blockIdx.x * MT;
    const int w    = tid >> 5;
    const int lane = tid & 31;
    const int g    = lane >> 2;
    const int t    = lane & 3;
    const int wm   = w & 3;        // m-quarter
    const int wh   = w >> 2;       // n-half (S) / cv-half (O)
    const int m0w  = wm * 32;
    const int n0w  = wh * 32;
    const int cv0w = wh * 128;

    const __half* Q = g_Q + (size_t)b * HW * CHD;
    const __half* K = g_K + (size_t)b * HW * CHD;
    const __half* V = g_V + (size_t)b * CIN * HW;

    const unsigned qsB = (unsigned)__cvta_generic_to_shared(Qs);
    const unsigned ksB = (unsigned)__cvta_generic_to_shared(Ks);
    const unsigned vsB = (unsigned)__cvta_generic_to_shared(Vs);
    const unsigned psB = (unsigned)__cvta_generic_to_shared(Ps);

    // ldmatrix per-lane offsets (in halfs)
    const int l15   = lane & 15;
    const int asel  = (lane >> 4) << 3;                  // A col select (0 or 8)
    const int brow4 = (lane & 7) + ((lane >> 4) << 3);   // x4-B row within 16
    const int bsel4 = ((lane >> 3) & 1) << 3;            // x4-B col select (0 or 8)
    const int a_q  = (m0w + l15) * QS_STR + asel;        // + mf*16*QS_STR + ks*16
    const int b_k4 = (n0w + brow4) * QS_STR + bsel4;     // + nfp*16*QS_STR + ks*16
    const int a_p  = (m0w + l15) * VS_STR + asel;        // + mf*16*VS_STR + kn*16
    const int b_v4 = (cv0w + brow4) * VS_STR + bsel4;    // + cfp*16*VS_STR + kn*16

    // ---- prologue: async-load Q tile + K tile 0 (one group) ----
    for (int idx = tid; idx < 128 * 16; idx += 256) {    // 128 rows x 16 chunks(8h)
        int r = idx >> 4, c8 = (idx & 15) << 3;
        cp_async16(qsB + (unsigned)(r * QS_STR + c8) * 2u, &Q[(size_t)(m0g + r) * CHD + c8]);
    }
    for (int idx = tid; idx < 64 * 16; idx += 256) {
        int r = idx >> 4, c8 = (idx & 15) << 3;
        cp_async16(ksB + (unsigned)(r * QS_STR + c8) * 2u, &K[(size_t)r * CHD + c8]);
    }
    cp_async_commit();

    // Register-resident softmax state: rows (m0w + mf*16 + g) and (+8)
    float rowM[2][2], rowL[2][2], alpha[2][2];
    #pragma unroll
    for (int mf = 0; mf < 2; mf++) {
        rowM[mf][0] = -1e30f; rowM[mf][1] = -1e30f;
        rowL[mf][0] = 0.0f;   rowL[mf][1] = 0.0f;
    }

    float oacc[2][16][4];
    #pragma unroll
    for (int mf = 0; mf < 2; mf++)
        #pragma unroll
        for (int cf = 0; cf < 16; cf++)
            #pragma unroll
            for (int e = 0; e < 4; e++) oacc[mf][cf][e] = 0.0f;

    for (int nt = 0; nt < HW; nt += NT) {
        __syncthreads();   // prior O-phase done (Vs/Ps free)

        // issue V(nt) loads (overlaps S-phase)
        for (int idx = tid; idx < 256 * 8; idx += 256) {  // 256 rows x 8 chunks
            int r = idx >> 3, c8 = (idx & 7) << 3;
            cp_async16(vsB + (unsigned)(r * VS_STR + c8) * 2u, &V[(size_t)r * HW + nt + c8]);
        }
        cp_async_commit();

        cp_async_wait1();  // K(nt) (+Q on iter 0) complete
        __syncthreads();   // K visible to all

        // ---- S = Q Kt  (8 ksteps of k16) ----
        float sacc[2][4][4] = {};
        #pragma unroll
        for (int ks = 0; ks < 8; ks++) {
            int kc = ks * 16;
            unsigned a[2][4];
            ldsm_x4(a[0][0], a[0][1], a[0][2], a[0][3], qsB + (unsigned)(a_q + kc) * 2u);
            ldsm_x4(a[1][0], a[1][1], a[1][2], a[1][3], qsB + (unsigned)(a_q + 16 * QS_STR + kc) * 2u);
            #pragma unroll
            for (int nfp = 0; nfp < 2; nfp++) {
                unsigned b0, b1, b2, b3;
                ldsm_x4(b0, b1, b2, b3, ksB + (unsigned)(b_k4 + nfp * 16 * QS_STR + kc) * 2u);
                mma_f16(sacc[0][2 * nfp],     a[0][0], a[0][1], a[0][2], a[0][3], b0, b1);
                mma_f16(sacc[1][2 * nfp],     a[1][0], a[1][1], a[1][2], a[1][3], b0, b1);
                mma_f16(sacc[0][2 * nfp + 1], a[0][0], a[0][1], a[0][2], a[0][3], b2, b3);
                mma_f16(sacc[1][2 * nfp + 1], a[1][0], a[1][1], a[1][2], a[1][3], b2, b3);
            }
        }

        // ---- per-warp partial row max ----
        float lm[2][2];
        #pragma unroll
        for (int mf = 0; mf < 2; mf++) {
            float lm0 = -1e30f, lm1 = -1e30f;
            #pragma unroll
            for (int nf = 0; nf < 4; nf++) {
                lm0 = fmaxf(lm0, fmaxf(sacc[mf][nf][0], sacc[mf][nf][1]));
                lm1 = fmaxf(lm1, fmaxf(sacc[mf][nf][2], sacc[mf][nf][3]));
            }
            lm0 = fmaxf(lm0, __shfl_xor_sync(0xffffffffu, lm0, 1));
            lm0 = fmaxf(lm0, __shfl_xor_sync(0xffffffffu, lm0, 2));
            lm1 = fmaxf(lm1, __shfl_xor_sync(0xffffffffu, lm1, 1));
            lm1 = fmaxf(lm1, __shfl_xor_sync(0xffffffffu, lm1, 2));
            lm[mf][0] = lm0; lm[mf][1] = lm1;
            if (t == 0) {
                pmax[wh * 128 + m0w + mf * 16 + g]     = lm0;
                pmax[wh * 128 + m0w + mf * 16 + g + 8] = lm1;
            }
        }
        __syncthreads();   // Ks consumed + pmax published

        // prefetch K(nt+NT) into Ks
        {
            int ntn = (nt + NT < HW) ? nt + NT : 0;
            for (int idx = tid; idx < 64 * 16; idx += 256) {
                int r = idx >> 4, c8 = (idx & 15) << 3;
                cp_async16(ksB + (unsigned)(r * QS_STR + c8) * 2u,
                           &K[(size_t)(ntn + r) * CHD + c8]);
            }
            cp_async_commit();
        }

        // ---- finalize rowM/alpha in registers ----
        const float* pmaxO = pmax + (wh ^ 1) * 128;
        #pragma unroll
        for (int mf = 0; mf < 2; mf++) {
            int r0 = m0w + mf * 16 + g;
            float nm0 = fmaxf(rowM[mf][0], fmaxf(lm[mf][0], pmaxO[r0]));
            float nm1 = fmaxf(rowM[mf][1], fmaxf(lm[mf][1], pmaxO[r0 + 8]));
            alpha[mf][0] = __expf(rowM[mf][0] - nm0);
            alpha[mf][1] = __expf(rowM[mf][1] - nm1);
            rowM[mf][0] = nm0; rowM[mf][1] = nm1;
        }

        // ---- P = exp(S - m) -> fp16, store + partial sums ----
        float ls[2][2];
        #pragma unroll
        for (int mf = 0; mf < 2; mf++) {
            int r0 = m0w + mf * 16 + g;
            float nm0 = rowM[mf][0], nm1 = rowM[mf][1];
            float ls0 = 0.0f, ls1 = 0.0f;
            #pragma unroll
            for (int nf = 0; nf < 4; nf++) {
                __half2 ph01 = __floats2half2_rn(__expf(sacc[mf][nf][0] - nm0),
                                                 __expf(sacc[mf][nf][1] - nm0));
                __half2 ph23 = __floats2half2_rn(__expf(sacc[mf][nf][2] - nm1),
                                                 __expf(sacc[mf][nf][3] - nm1));
                float2 pf01 = __half22float2(ph01);
                float2 pf23 = __half22float2(ph23);
                ls0 += pf01.x + pf01.y;
                ls1 += pf23.x + pf23.y;
                int n = n0w + nf * 8 + 2 * t;
                *(__half2*)&Ps[r0 * VS_STR + n]       = ph01;
                *(__half2*)&Ps[(r0 + 8) * VS_STR + n] = ph23;
            }
            ls0 += __shfl_xor_sync(0xffffffffu, ls0, 1);
            ls0 += __shfl_xor_sync(0xffffffffu, ls0, 2);
            ls1 += __shfl_xor_sync(0xffffffffu, ls1, 1);
            ls1 += __shfl_xor_sync(0xffffffffu, ls1, 2);
            ls[mf][0] = ls0; ls[mf][1] = ls1;
            if (t == 0) {
                psum[wh * 128 + r0]     = ls0;
                psum[wh * 128 + r0 + 8] = ls1;
            }
        }
        cp_async_wait1();  // V(nt) complete (K prefetch in flight)
        __syncthreads();   // Ps/psum published + Vs visible

        // ---- rowL update in registers ----
        const float* psumO = psum + (wh ^ 1) * 128;
        #pragma unroll
        for (int mf = 0; mf < 2; mf++) {
            int r0 = m0w + mf * 16 + g;
            rowL[mf][0] = rowL[mf][0] * alpha[mf][0] + ls[mf][0] + psumO[r0];
            rowL[mf][1] = rowL[mf][1] * alpha[mf][1] + ls[mf][1] + psumO[r0 + 8];
        }

        // ---- O = O*alpha + P Vt  (4 ksteps of k16) ----
        #pragma unroll
        for (int mf = 0; mf < 2; mf++) {
            float al0 = alpha[mf][0];
            float al1 = alpha[mf][1];
            #pragma unroll
            for (int cf = 0; cf < 16; cf++) {
                oacc[mf][cf][0] *= al0; oacc[mf][cf][1] *= al0;
                oacc[mf][cf][2] *= al1; oacc[mf][cf][3] *= al1;
            }
        }
        #pragma unroll
        for (int kn = 0; kn < 4; kn++) {
            int kc = kn * 16;
            unsigned a[2][4];
            ldsm_x4(a[0][0], a[0][1], a[0][2], a[0][3], psB + (unsigned)(a_p + kc) * 2u);
            ldsm_x4(a[1][0], a[1][1], a[1][2], a[1][3], psB + (unsigned)(a_p + 16 * VS_STR + kc) * 2u);
            #pragma unroll
            for (int cfp = 0; cfp < 8; cfp++) {
                unsigned b0, b1, b2, b3;
                ldsm_x4(b0, b1, b2, b3, vsB + (unsigned)(b_v4 + cfp * 16 * VS_STR + kc) * 2u);
                mma_f16(oacc[0][2 * cfp],     a[0][0], a[0][1], a[0][2], a[0][3], b0, b1);
                mma_f16(oacc[1][2 * cfp],     a[1][0], a[1][1], a[1][2], a[1][3], b0, b1);
                mma_f16(oacc[0][2 * cfp + 1], a[0][0], a[0][1], a[0][2], a[0][3], b2, b3);
                mma_f16(oacc[1][2 * cfp + 1], a[1][0], a[1][1], a[1][2], a[1][3], b2, b3);
            }
        }
    }

    // ---- epilogue: normalize (register rowL), residual, store ----
    #pragma unroll
    for (int mf = 0; mf < 2; mf++) {
        int r0 = m0w + mf * 16 + g;
        float il0 = 1.0f / rowL[mf][0];
        float il1 = 1.0f / rowL[mf][1];
        int mg = m0g + r0;
        #pragma unroll
        for (int cf = 0; cf < 16; cf++) {
            int cv = cv0w + cf * 8 + 2 * t;
            size_t i0 = ((size_t)(b * CIN + cv)) * HW + mg;
            size_t i1 = i0 + HW;
            out[i0]     = oacc[mf][cf][0] * il0 + resid[i0];
            out[i1]     = oacc[mf][cf][1] * il0 + resid[i1];
            out[i0 + 8] = oacc[mf][cf][2] * il1 + resid[i0 + 8];
            out[i1 + 8] = oacc[mf][cf][3] * il1 + resid[i1 + 8];
        }
    }
}

// ---------------------------------------------------------------------------
extern "C" void kernel_launch(void* const* d_in, const int* in_sizes, int n_in,
                              void* d_out, int out_size) {
    const float* a  = (const float*)d_in[0];
    const float* p  = (const float*)d_in[1];
    const float* Wq = (const float*)d_in[2];
    const float* bq = (const float*)d_in[3];
    const float* Wk = (const float*)d_in[4];
    const float* bk = (const float*)d_in[5];
    const float* Wv = (const float*)d_in[6];
    const float* bv = (const float*)d_in[7];
    float* out = (float*)d_out;

    __half *dQ, *dK, *dV;
    cudaGetSymbolAddress((void**)&dQ, g_Q);
    cudaGetSymbolAddress((void**)&dK, g_K);
    cudaGetSymbolAddress((void**)&dV, g_V);

    dim3 blk(256);
    proj_t_kernel<<<dim3(HW / 64, CHD / 64, BB), blk>>>(Wq, bq, a, dQ, CHD);
    proj_t_kernel<<<dim3(HW / 64, CHD / 64, BB), blk>>>(Wk, bk, p, dK, CHD);
    proj_kernel  <<<dim3(HW / 64, CIN / 64, BB), blk>>>(Wv, bv, p, dV, CIN);

    const int smem = (128 * QS_STR + 64 * QS_STR + 256 * VS_STR + 128 * VS_STR) * 2 + 512 * 4;
    cudaFuncSetAttribute(attn_kernel, cudaFuncAttributeMaxDynamicSharedMemorySize, smem);
    attn_kernel<<<dim3(HW / MT, BB), blk, smem>>>(a, out);
}